// round 3
// baseline (speedup 1.0000x reference)
#include <cuda_runtime.h>
#include <math.h>

#define NB     32
#define NA     33600
#define K_TOP  1000
#define NBINS  2048    // coarse bins: score_bits >> 19  (scores in (0,1) -> bin <= 2031)
#define NSUB   2048    // sub bins: bits[18:8]
#define NCAND  2048

// scratch (static device globals — no allocation)
__device__ float        g_scores[NB * NA];        // 4.3 MB, L2-resident
__device__ unsigned int g_hist[NB * NBINS];       // 256 KB per-batch coarse histograms
__device__ int          g_keep[NB * K_TOP];

// Bitwise match of XLA GPU logistic: 1/(1+exp(-x)) with libdevice expf and
// IEEE div.rn (nvcc defaults, no fast-math). DO NOT refactor algebraically —
// output ordering must be bit-exact vs reference (rel_err 5e-9 confirms).
__device__ __forceinline__ float sigref(float x) {
    return 1.0f / (1.0f + expf(-x));
}

// ---------------------------------------------------------------------------
// Kernel 0: zero the global histograms
// ---------------------------------------------------------------------------
__global__ void zero_hist() {
    int i = blockIdx.x * blockDim.x + threadIdx.x;
    if (i < NB * NBINS) g_hist[i] = 0u;
}

// ---------------------------------------------------------------------------
// Kernel 1: score[b,a] = sigmoid(cls)*sigmoid(obj)  (+ global histogram REDG)
// float4-vectorized; level boundaries divisible by 4.
// ---------------------------------------------------------------------------
__global__ void score_kernel(const float* __restrict__ cls0, const float* __restrict__ cls1,
                             const float* __restrict__ cls2,
                             const float* __restrict__ obj0, const float* __restrict__ obj1,
                             const float* __restrict__ obj2) {
    int i4 = blockIdx.x * blockDim.x + threadIdx.x;
    if (i4 >= NB * NA / 4) return;
    int b  = i4 / (NA / 4);
    int a4 = i4 - b * (NA / 4);
    const float4 *cp, *op;
    int p4;
    if (a4 < 6400)      { cp = (const float4*)cls0 + b * 6400; op = (const float4*)obj0 + b * 6400; p4 = a4; }
    else if (a4 < 8000) { cp = (const float4*)cls1 + b * 1600; op = (const float4*)obj1 + b * 1600; p4 = a4 - 6400; }
    else                { cp = (const float4*)cls2 + b * 400;  op = (const float4*)obj2 + b * 400;  p4 = a4 - 8000; }
    float4 c = cp[p4];
    float4 o = op[p4];
    float4 r;
    r.x = sigref(c.x) * sigref(o.x);
    r.y = sigref(c.y) * sigref(o.y);
    r.z = sigref(c.z) * sigref(o.z);
    r.w = sigref(c.w) * sigref(o.w);
    ((float4*)g_scores)[i4] = r;
    unsigned int* h = g_hist + b * NBINS;
    atomicAdd(&h[__float_as_uint(r.x) >> 19], 1u);
    atomicAdd(&h[__float_as_uint(r.y) >> 19], 1u);
    atomicAdd(&h[__float_as_uint(r.z) >> 19], 1u);
    atomicAdd(&h[__float_as_uint(r.w) >> 19], 1u);
}

// ---------------------------------------------------------------------------
// Kernel 2: exact sorted top-1000 per batch (one CTA per batch, 1024 threads)
// ---------------------------------------------------------------------------

// Find threshold bin (descending): largest bin T with
// count(bins > T) < K <= count(bins >= T). nbins must be 2048 here (per=2).
__device__ void find_thresh(const unsigned int* hist, int nbins, int K, int tid,
                            int* wsum, int* s_bin, int* s_above) {
    int per  = nbins >> 10;
    int base = nbins - 1 - tid * per;
    int tsum = 0;
    for (int q = 0; q < per; q++) tsum += (int)hist[base - q];

    int lane = tid & 31, wid = tid >> 5;
    int x = tsum;
#pragma unroll
    for (int d = 1; d < 32; d <<= 1) {
        int n = __shfl_up_sync(0xffffffffu, x, d);
        if (lane >= d) x += n;
    }
    if (lane == 31) wsum[wid] = x;
    __syncthreads();
    if (wid == 0) {
        int w = wsum[lane];
#pragma unroll
        for (int d = 1; d < 32; d <<= 1) {
            int n = __shfl_up_sync(0xffffffffu, w, d);
            if (lane >= d) w += n;
        }
        wsum[lane] = w;
    }
    __syncthreads();
    int excl = (wid == 0 ? 0 : wsum[wid - 1]) + (x - tsum);

    if (excl < K && excl + tsum >= K) {     // exactly one thread
        int c = excl;
        for (int q = 0; q < per; q++) {
            int bin = base - q;
            int h = (int)hist[bin];
            if (c + h >= K) { *s_bin = bin; *s_above = c; break; }
            c += h;
        }
    }
    __syncthreads();
}

__global__ __launch_bounds__(1024) void topk_kernel(float* __restrict__ dout) {
    __shared__ unsigned int       hist[NBINS];    // 8 KB (coarse copy, then reused)
    __shared__ unsigned int       sub[NSUB];      // 8 KB
    __shared__ unsigned long long cand[NCAND];    // 16 KB
    __shared__ int  wsum[32];
    __shared__ int  s_bin, s_above;
    __shared__ unsigned int s_cnt;

    int b = blockIdx.x;
    int tid = threadIdx.x;
    const uint4* sv = (const uint4*)(g_scores + b * NA);

    // Phase A: coarse histogram was built by score_kernel; copy & threshold.
    for (int q = tid; q < NBINS; q += 1024) {
        hist[q] = g_hist[b * NBINS + q];
        sub[q]  = 0u;
    }
    __syncthreads();
    find_thresh(hist, NBINS, K_TOP, tid, wsum, &s_bin, &s_above);
    int T = s_bin;
    int need2 = K_TOP - s_above;
    __syncthreads();

    // Phase B: sub-histogram of bin-T members on bits[18:8] (few-K atomics).
    for (int q = tid; q < NA / 4; q += 1024) {
        uint4 v = sv[q];
        if ((int)(v.x >> 19) == T) atomicAdd(&sub[(v.x >> 8) & 2047u], 1u);
        if ((int)(v.y >> 19) == T) atomicAdd(&sub[(v.y >> 8) & 2047u], 1u);
        if ((int)(v.z >> 19) == T) atomicAdd(&sub[(v.z >> 8) & 2047u], 1u);
        if ((int)(v.w >> 19) == T) atomicAdd(&sub[(v.w >> 8) & 2047u], 1u);
    }
    __syncthreads();
    find_thresh(sub, NSUB, need2, tid, wsum, &s_bin, &s_above);
    unsigned int cut = ((unsigned int)T << 19) | ((unsigned int)s_bin << 8);
    if (tid == 0) s_cnt = 0u;
    __syncthreads();

    // Phase C: compact candidates (bits >= cut) as sortable 64-bit keys.
    // key = (bits << 32) | ~index : bigger key == better (score desc, idx asc).
    for (int q = tid; q < NA / 4; q += 1024) {
        uint4 v = sv[q];
        int a0 = q * 4;
#pragma unroll
        for (int e = 0; e < 4; e++) {
            unsigned int bits = (e == 0) ? v.x : (e == 1) ? v.y : (e == 2) ? v.z : v.w;
            if (bits >= cut) {
                unsigned int pos = atomicAdd(&s_cnt, 1u);
                if (pos < NCAND)
                    cand[pos] = ((unsigned long long)bits << 32) |
                                (unsigned long long)(0xFFFFFFFFu - (unsigned int)(a0 + e));
            }
        }
    }
    __syncthreads();
    int cnt = (int)s_cnt; if (cnt > NCAND) cnt = NCAND;

    // Phase D: rank by counting (keys unique -> ranks form a permutation).
    // Barrier-free smem broadcast loop, cnt ~= 1000-1100 iterations.
    unsigned long long k0 = (tid < cnt)        ? cand[tid]        : 0ull;
    unsigned long long k1 = (tid + 1024 < cnt) ? cand[tid + 1024] : 0ull;
    int r0 = 0, r1 = 0;
#pragma unroll 4
    for (int j = 0; j < cnt; j++) {
        unsigned long long kj = cand[j];
        r0 += (kj > k0);
        r1 += (kj > k1);
    }

    // Phase E: emit kept indices + score column of dets.
    if (tid < cnt && r0 < K_TOP) {
        unsigned int bits = (unsigned int)(k0 >> 32);
        unsigned int a    = 0xFFFFFFFFu - (unsigned int)(k0 & 0xFFFFFFFFull);
        g_keep[b * K_TOP + r0] = (int)a;
        dout[b * (K_TOP * 5) + r0 * 5 + 4] = __uint_as_float(bits);
    }
    if (tid + 1024 < cnt && r1 < K_TOP) {
        unsigned int bits = (unsigned int)(k1 >> 32);
        unsigned int a    = 0xFFFFFFFFu - (unsigned int)(k1 & 0xFFFFFFFFull);
        g_keep[b * K_TOP + r1] = (int)a;
        dout[b * (K_TOP * 5) + r1 * 5 + 4] = __uint_as_float(bits);
    }
}

// ---------------------------------------------------------------------------
// Kernel 3: decode kept anchors. 18 tasks per detection: 17 kpts + 1 bbox.
// ---------------------------------------------------------------------------
__global__ void decode_kernel(const float* __restrict__ bbox0, const float* __restrict__ bbox1,
                              const float* __restrict__ bbox2,
                              const float* __restrict__ kpt0,  const float* __restrict__ kpt1,
                              const float* __restrict__ kpt2,
                              const float* __restrict__ vis0,  const float* __restrict__ vis1,
                              const float* __restrict__ vis2,
                              float* __restrict__ dout) {
    const int NTASK = NB * K_TOP * 18;
    int task = blockIdx.x * blockDim.x + threadIdx.x;
    if (task >= NTASK) return;
    int det = task / 18;
    int sub = task - det * 18;
    int b   = det / K_TOP;
    int a   = g_keep[det];

    int p, HW, l;
    float s, px, py;
    if (a < 25600)      { p = a;         HW = 25600; s = 8.0f;  l = 0; px = (float)(p % 160) * 8.0f;  py = (float)(p / 160) * 8.0f;  }
    else if (a < 32000) { p = a - 25600; HW = 6400;  s = 16.0f; l = 1; px = (float)(p % 80)  * 16.0f; py = (float)(p / 80)  * 16.0f; }
    else                { p = a - 32000; HW = 1600;  s = 32.0f; l = 2; px = (float)(p % 40)  * 32.0f; py = (float)(p / 40)  * 32.0f; }

    if (sub < 17) {
        int k = sub;
        const float* kp = (l == 0) ? kpt0 : (l == 1) ? kpt1 : kpt2;
        const float* vp = (l == 0) ? vis0 : (l == 1) ? vis1 : vis2;
        float kx = kp[(b * 34 + 2 * k)     * HW + p];
        float ky = kp[(b * 34 + 2 * k + 1) * HW + p];
        float v  = vp[(b * 17 + k)         * HW + p];
        int off = NB * K_TOP * 5 + det * 51 + k * 3;
        dout[off + 0] = kx * s + px;
        dout[off + 1] = ky * s + py;
        dout[off + 2] = sigref(v);
    } else {
        const float* bp = (l == 0) ? bbox0 : (l == 1) ? bbox1 : bbox2;
        float bx = bp[(b * 4 + 0) * HW + p];
        float by = bp[(b * 4 + 1) * HW + p];
        float bw = bp[(b * 4 + 2) * HW + p];
        float bh = bp[(b * 4 + 3) * HW + p];
        float x  = bx * s + px;
        float y  = by * s + py;
        float hw = expf(bw) * s * 0.5f;
        float hh = expf(bh) * s * 0.5f;
        int off = det * 5;
        dout[off + 0] = x - hw;
        dout[off + 1] = y - hh;
        dout[off + 2] = x + hw;
        dout[off + 3] = y + hh;
    }
}

// ---------------------------------------------------------------------------
extern "C" void kernel_launch(void* const* d_in, const int* in_sizes, int n_in,
                              void* d_out, int out_size) {
    const float* cls0  = (const float*)d_in[0];
    const float* cls1  = (const float*)d_in[1];
    const float* cls2  = (const float*)d_in[2];
    const float* bbox0 = (const float*)d_in[3];
    const float* bbox1 = (const float*)d_in[4];
    const float* bbox2 = (const float*)d_in[5];
    const float* obj0  = (const float*)d_in[6];
    const float* obj1  = (const float*)d_in[7];
    const float* obj2  = (const float*)d_in[8];
    const float* kpt0  = (const float*)d_in[9];
    const float* kpt1  = (const float*)d_in[10];
    const float* kpt2  = (const float*)d_in[11];
    const float* vis0  = (const float*)d_in[12];
    const float* vis1  = (const float*)d_in[13];
    const float* vis2  = (const float*)d_in[14];
    float* dout = (float*)d_out;

    zero_hist<<<(NB * NBINS + 1023) / 1024, 1024>>>();
    score_kernel<<<(NB * NA / 4 + 255) / 256, 256>>>(cls0, cls1, cls2, obj0, obj1, obj2);
    topk_kernel<<<NB, 1024>>>(dout);
    decode_kernel<<<(NB * K_TOP * 18 + 255) / 256, 256>>>(bbox0, bbox1, bbox2,
                                                          kpt0, kpt1, kpt2,
                                                          vis0, vis1, vis2, dout);
}

// round 4
// speedup vs baseline: 1.5115x; 1.5115x over previous
#include <cuda_runtime.h>
#include <math.h>

#define NB     32
#define NA     33600
#define K_TOP  1000
#define NBINS  2048    // coarse bins: score_bits >> 19 (scores in (0,1) -> bin <= 2031)
#define NSUB   2048    // refine bins: bits[18:8] (only used if coarse bin overflows)
#define NCAND  2048

// scratch (static device globals — no allocation)
__device__ float g_scores[NB * NA];   // 4.3 MB, L2-resident
__device__ int   g_keep[NB * K_TOP];

// Bitwise match of XLA GPU logistic: 1/(1+exp(-x)) with libdevice expf and
// IEEE div.rn (nvcc defaults, no fast-math). DO NOT refactor algebraically —
// output ordering must be bit-exact vs reference (rel_err 5e-9 confirms).
__device__ __forceinline__ float sigref(float x) {
    return 1.0f / (1.0f + expf(-x));
}

// ---------------------------------------------------------------------------
// Kernel 1: score[b,a] = sigmoid(cls)*sigmoid(obj), float4-vectorized.
// (R2 version: measured 6.8us, no atomics.)
// ---------------------------------------------------------------------------
__global__ void score_kernel(const float* __restrict__ cls0, const float* __restrict__ cls1,
                             const float* __restrict__ cls2,
                             const float* __restrict__ obj0, const float* __restrict__ obj1,
                             const float* __restrict__ obj2) {
    int i4 = blockIdx.x * blockDim.x + threadIdx.x;
    if (i4 >= NB * NA / 4) return;
    int b  = i4 / (NA / 4);
    int a4 = i4 - b * (NA / 4);
    const float4 *cp, *op;
    int p4;
    if (a4 < 6400)      { cp = (const float4*)cls0 + b * 6400; op = (const float4*)obj0 + b * 6400; p4 = a4; }
    else if (a4 < 8000) { cp = (const float4*)cls1 + b * 1600; op = (const float4*)obj1 + b * 1600; p4 = a4 - 6400; }
    else                { cp = (const float4*)cls2 + b * 400;  op = (const float4*)obj2 + b * 400;  p4 = a4 - 8000; }
    float4 c = cp[p4];
    float4 o = op[p4];
    float4 r;
    r.x = sigref(c.x) * sigref(o.x);
    r.y = sigref(c.y) * sigref(o.y);
    r.z = sigref(c.z) * sigref(o.z);
    r.w = sigref(c.w) * sigref(o.w);
    ((float4*)g_scores)[i4] = r;
}

// ---------------------------------------------------------------------------
// Kernel 2: exact sorted top-1000 per batch (one CTA per batch, 1024 threads)
// ---------------------------------------------------------------------------

// Find threshold bin (descending): largest bin T with
// count(bins > T) < K <= count(bins >= T). nbins = 2048 (per = 2).
__device__ void find_thresh(const unsigned int* hist, int nbins, int K, int tid,
                            int* wsum, int* s_bin, int* s_above) {
    int per  = nbins >> 10;
    int base = nbins - 1 - tid * per;
    int tsum = 0;
    for (int q = 0; q < per; q++) tsum += (int)hist[base - q];

    int lane = tid & 31, wid = tid >> 5;
    int x = tsum;
#pragma unroll
    for (int d = 1; d < 32; d <<= 1) {
        int n = __shfl_up_sync(0xffffffffu, x, d);
        if (lane >= d) x += n;
    }
    if (lane == 31) wsum[wid] = x;
    __syncthreads();
    if (wid == 0) {
        int w = wsum[lane];
#pragma unroll
        for (int d = 1; d < 32; d <<= 1) {
            int n = __shfl_up_sync(0xffffffffu, w, d);
            if (lane >= d) w += n;
        }
        wsum[lane] = w;
    }
    __syncthreads();
    int excl = (wid == 0 ? 0 : wsum[wid - 1]) + (x - tsum);

    if (excl < K && excl + tsum >= K) {     // exactly one thread
        int c = excl;
        for (int q = 0; q < per; q++) {
            int bin = base - q;
            int h = (int)hist[bin];
            if (c + h >= K) { *s_bin = bin; *s_above = c; break; }
            c += h;
        }
    }
    __syncthreads();
}

__global__ __launch_bounds__(1024) void topk_kernel(float* __restrict__ dout) {
    __shared__ unsigned int       hist[NBINS];    // 8 KB (coarse, then refine)
    __shared__ unsigned long long cand[NCAND];    // 16 KB
    __shared__ int  wsum[32];
    __shared__ int  s_bin, s_above;
    __shared__ unsigned int s_cnt;

    int b = blockIdx.x;
    int tid = threadIdx.x;
    const uint4* sv = (const uint4*)(g_scores + b * NA);

    // Phase 1: coarse histogram on bits >> 19 (uint4 loads from L2)
    for (int q = tid; q < NBINS; q += 1024) hist[q] = 0u;
    __syncthreads();
    for (int q = tid; q < NA / 4; q += 1024) {
        uint4 v = sv[q];
        atomicAdd(&hist[v.x >> 19], 1u);
        atomicAdd(&hist[v.y >> 19], 1u);
        atomicAdd(&hist[v.z >> 19], 1u);
        atomicAdd(&hist[v.w >> 19], 1u);
    }
    __syncthreads();
    find_thresh(hist, NBINS, K_TOP, tid, wsum, &s_bin, &s_above);
    int T = s_bin;
    int need2 = K_TOP - s_above;
    int binT_count = (int)hist[T];
    __syncthreads();

    unsigned int cut;
    if (s_above + binT_count <= NCAND) {
        // Common case: all of bin T fits in the candidate buffer -> no refine.
        cut = (unsigned int)T << 19;
    } else {
        // Rare: refine bin T on bits[18:8].
        for (int q = tid; q < NSUB; q += 1024) hist[q] = 0u;
        __syncthreads();
        for (int q = tid; q < NA / 4; q += 1024) {
            uint4 v = sv[q];
            if ((int)(v.x >> 19) == T) atomicAdd(&hist[(v.x >> 8) & 2047u], 1u);
            if ((int)(v.y >> 19) == T) atomicAdd(&hist[(v.y >> 8) & 2047u], 1u);
            if ((int)(v.z >> 19) == T) atomicAdd(&hist[(v.z >> 8) & 2047u], 1u);
            if ((int)(v.w >> 19) == T) atomicAdd(&hist[(v.w >> 8) & 2047u], 1u);
        }
        __syncthreads();
        find_thresh(hist, NSUB, need2, tid, wsum, &s_bin, &s_above);
        cut = ((unsigned int)T << 19) | ((unsigned int)s_bin << 8);
        __syncthreads();
    }

    // Phase 2: compact candidates (bits >= cut) as sortable 64-bit keys.
    // key = (bits << 32) | ~index : bigger key == better (score desc, idx asc).
    if (tid == 0) s_cnt = 0u;
    __syncthreads();
    for (int q = tid; q < NA / 4; q += 1024) {
        uint4 v = sv[q];
        int a0 = q * 4;
#pragma unroll
        for (int e = 0; e < 4; e++) {
            unsigned int bits = (e == 0) ? v.x : (e == 1) ? v.y : (e == 2) ? v.z : v.w;
            if (bits >= cut) {
                unsigned int pos = atomicAdd(&s_cnt, 1u);
                if (pos < NCAND)
                    cand[pos] = ((unsigned long long)bits << 32) |
                                (unsigned long long)(0xFFFFFFFFu - (unsigned int)(a0 + e));
            }
        }
    }
    __syncthreads();
    int cnt = (int)s_cnt; if (cnt > NCAND) cnt = NCAND;
    for (int q = cnt + tid; q < NCAND; q += 1024) cand[q] = 0ull;
    __syncthreads();

    // Phase 3: bitonic sort 2048 keys, descending (known-correct R1 version).
    for (unsigned int k = 2; k <= NCAND; k <<= 1) {
        for (unsigned int j = k >> 1; j > 0; j >>= 1) {
            for (unsigned int i = tid; i < NCAND; i += 1024) {
                unsigned int ixj = i ^ j;
                if (ixj > i) {
                    unsigned long long A = cand[i], B = cand[ixj];
                    bool desc = ((i & k) == 0);
                    if (desc ? (A < B) : (A > B)) { cand[i] = B; cand[ixj] = A; }
                }
            }
            __syncthreads();
        }
    }

    // Phase 4: emit kept indices + score column of dets
    if (tid < K_TOP) {
        unsigned long long key = cand[tid];
        unsigned int bits = (unsigned int)(key >> 32);
        unsigned int a    = 0xFFFFFFFFu - (unsigned int)(key & 0xFFFFFFFFull);
        g_keep[b * K_TOP + tid] = (int)a;
        dout[b * (K_TOP * 5) + tid * 5 + 4] = __uint_as_float(bits);
    }
}

// ---------------------------------------------------------------------------
// Kernel 3: decode kept anchors. Channel-major tasking: det is the FAST index
// so a warp's 32 lanes gather the same channel for 32 consecutive detections
// (same ~100KB row region -> DRAM page locality), instead of 18 rows/warp.
// ---------------------------------------------------------------------------
#define NDET (NB * K_TOP)

__global__ void decode_kernel(const float* __restrict__ bbox0, const float* __restrict__ bbox1,
                              const float* __restrict__ bbox2,
                              const float* __restrict__ kpt0,  const float* __restrict__ kpt1,
                              const float* __restrict__ kpt2,
                              const float* __restrict__ vis0,  const float* __restrict__ vis1,
                              const float* __restrict__ vis2,
                              float* __restrict__ dout) {
    const int NTASK = NDET * 18;
    int task = blockIdx.x * blockDim.x + threadIdx.x;
    if (task >= NTASK) return;
    int det = task % NDET;          // fast index -> warp = 32 consecutive dets
    int sub = task / NDET;          // 0..16 = keypoint, 17 = bbox
    int b   = det / K_TOP;
    int a   = g_keep[det];

    int p, HW, l;
    float s, px, py;
    if (a < 25600)      { p = a;         HW = 25600; s = 8.0f;  l = 0; px = (float)(p % 160) * 8.0f;  py = (float)(p / 160) * 8.0f;  }
    else if (a < 32000) { p = a - 25600; HW = 6400;  s = 16.0f; l = 1; px = (float)(p % 80)  * 16.0f; py = (float)(p / 80)  * 16.0f; }
    else                { p = a - 32000; HW = 1600;  s = 32.0f; l = 2; px = (float)(p % 40)  * 32.0f; py = (float)(p / 40)  * 32.0f; }

    if (sub < 17) {
        int k = sub;
        const float* kp = (l == 0) ? kpt0 : (l == 1) ? kpt1 : kpt2;
        const float* vp = (l == 0) ? vis0 : (l == 1) ? vis1 : vis2;
        float kx = kp[(b * 34 + 2 * k)     * HW + p];
        float ky = kp[(b * 34 + 2 * k + 1) * HW + p];
        float v  = vp[(b * 17 + k)         * HW + p];
        int off = NDET * 5 + det * 51 + k * 3;
        dout[off + 0] = kx * s + px;
        dout[off + 1] = ky * s + py;
        dout[off + 2] = sigref(v);
    } else {
        const float* bp = (l == 0) ? bbox0 : (l == 1) ? bbox1 : bbox2;
        float bx = bp[(b * 4 + 0) * HW + p];
        float by = bp[(b * 4 + 1) * HW + p];
        float bw = bp[(b * 4 + 2) * HW + p];
        float bh = bp[(b * 4 + 3) * HW + p];
        float x  = bx * s + px;
        float y  = by * s + py;
        float hw = expf(bw) * s * 0.5f;
        float hh = expf(bh) * s * 0.5f;
        int off = det * 5;
        dout[off + 0] = x - hw;
        dout[off + 1] = y - hh;
        dout[off + 2] = x + hw;
        dout[off + 3] = y + hh;
    }
}

// ---------------------------------------------------------------------------
extern "C" void kernel_launch(void* const* d_in, const int* in_sizes, int n_in,
                              void* d_out, int out_size) {
    const float* cls0  = (const float*)d_in[0];
    const float* cls1  = (const float*)d_in[1];
    const float* cls2  = (const float*)d_in[2];
    const float* bbox0 = (const float*)d_in[3];
    const float* bbox1 = (const float*)d_in[4];
    const float* bbox2 = (const float*)d_in[5];
    const float* obj0  = (const float*)d_in[6];
    const float* obj1  = (const float*)d_in[7];
    const float* obj2  = (const float*)d_in[8];
    const float* kpt0  = (const float*)d_in[9];
    const float* kpt1  = (const float*)d_in[10];
    const float* kpt2  = (const float*)d_in[11];
    const float* vis0  = (const float*)d_in[12];
    const float* vis1  = (const float*)d_in[13];
    const float* vis2  = (const float*)d_in[14];
    float* dout = (float*)d_out;

    score_kernel<<<(NB * NA / 4 + 255) / 256, 256>>>(cls0, cls1, cls2, obj0, obj1, obj2);
    topk_kernel<<<NB, 1024>>>(dout);
    decode_kernel<<<(NDET * 18 + 255) / 256, 256>>>(bbox0, bbox1, bbox2,
                                                    kpt0, kpt1, kpt2,
                                                    vis0, vis1, vis2, dout);
}